// round 9
// baseline (speedup 1.0000x reference)
#include <cuda_runtime.h>
#include <cstdint>

#define S_    32
#define IN_   2048
#define OUT_  2048
#define TPB   256
#define SGRP  8                   // samples per block
#define QBLK  (S_ / SGRP)         // 4 s-quarters -> grid = OUT_ * QBLK

// ---------------------------------------------------------------------------
// Host-side threefry2x32 (subkey derivation for jax.random.key(42) only)
// ---------------------------------------------------------------------------
static inline uint32_t h_rotl32(uint32_t x, int r) {
    return (x << r) | (x >> (32 - r));
}
static inline void h_round(uint32_t& x0, uint32_t& x1, int r) {
    x0 += x1; x1 = h_rotl32(x1, r); x1 ^= x0;
}
static void h_threefry2x32(uint32_t k0, uint32_t k1, uint32_t c0, uint32_t c1,
                           uint32_t& o0, uint32_t& o1)
{
    const uint32_t k2 = k0 ^ k1 ^ 0x1BD11BDAu;
    uint32_t x0 = c0 + k0, x1 = c1 + k1;
    h_round(x0,x1,13); h_round(x0,x1,15); h_round(x0,x1,26); h_round(x0,x1,6);
    x0 += k1; x1 += k2 + 1u;
    h_round(x0,x1,17); h_round(x0,x1,29); h_round(x0,x1,16); h_round(x0,x1,24);
    x0 += k2; x1 += k0 + 2u;
    h_round(x0,x1,13); h_round(x0,x1,15); h_round(x0,x1,26); h_round(x0,x1,6);
    x0 += k0; x1 += k1 + 3u;
    h_round(x0,x1,17); h_round(x0,x1,29); h_round(x0,x1,16); h_round(x0,x1,24);
    x0 += k1; x1 += k2 + 4u;
    h_round(x0,x1,13); h_round(x0,x1,15); h_round(x0,x1,26); h_round(x0,x1,6);
    x0 += k2; x1 += k0 + 5u;
    o0 = x0; o1 = x1;
}

// ---------------------------------------------------------------------------
// Param structs (opaque to ptxas -> no strength reduction).
// ---------------------------------------------------------------------------
struct TFKeys {
    uint32_t k0, k1, k2;
    uint32_t j1, j2, j3, j4, j5;   // k2+1, k0+2, k1+3, k2+4, k0+5
};
struct RotM {                      // 2^R for each rotation amount (opaque regs)
    uint32_t m13, m15, m26, m6, m17, m29, m16, m24;
};

// ---------------------------------------------------------------------------
// Device threefry round, wide-multiply rotate variant:
//   x0 += x1                 IMAD        (fma pipe, opaque one)
//   p  = x1 * m  (wide)      IMAD.WIDE   (fma pipe, opaque m, forced asm)
//   x1 = (p.lo | p.hi) ^ x0  single LOP3 (alu pipe)
// Only 1 alu op per round (LOP3); rotates leave the half-rate alu pipe.
// ---------------------------------------------------------------------------
__device__ __forceinline__ uint32_t addi(uint32_t a, uint32_t b, uint32_t one) {
    return a * one + b;            // IMAD -> fma pipe
}
__device__ __forceinline__ uint64_t mulwide(uint32_t a, uint32_t b) {
    uint64_t r; asm("mul.wide.u32 %0, %1, %2;" : "=l"(r) : "r"(a), "r"(b)); return r;
}
__device__ __forceinline__ void tfrm(uint32_t& x0, uint32_t& x1, uint32_t m, uint32_t one) {
    x0 = addi(x0, x1, one);
    const uint64_t p = mulwide(x1, m);
    x1 = (((uint32_t)p) | ((uint32_t)(p >> 32))) ^ x0;
}

__device__ __forceinline__ uint32_t threefry_from_x1(const TFKeys k, uint32_t x1,
                                                     uint32_t one, const RotM rm) {
    uint32_t x0 = k.k0;            // c0 == 0

    tfrm(x0,x1,rm.m13,one); tfrm(x0,x1,rm.m15,one); tfrm(x0,x1,rm.m26,one); tfrm(x0,x1,rm.m6,one);
    x0 = addi(x0, k.k1, one); x1 = addi(x1, k.j1, one);
    tfrm(x0,x1,rm.m17,one); tfrm(x0,x1,rm.m29,one); tfrm(x0,x1,rm.m16,one); tfrm(x0,x1,rm.m24,one);
    x0 = addi(x0, k.k2, one); x1 = addi(x1, k.j2, one);
    tfrm(x0,x1,rm.m13,one); tfrm(x0,x1,rm.m15,one); tfrm(x0,x1,rm.m26,one); tfrm(x0,x1,rm.m6,one);
    x0 = addi(x0, k.k0, one); x1 = addi(x1, k.j3, one);
    tfrm(x0,x1,rm.m17,one); tfrm(x0,x1,rm.m29,one); tfrm(x0,x1,rm.m16,one); tfrm(x0,x1,rm.m24,one);
    x0 = addi(x0, k.k1, one); x1 = addi(x1, k.j4, one);
    tfrm(x0,x1,rm.m13,one); tfrm(x0,x1,rm.m15,one); tfrm(x0,x1,rm.m26,one); tfrm(x0,x1,rm.m6,one);
    x0 = addi(x0, k.k2, one); x1 = addi(x1, k.j5, one);

    return x0 ^ x1;
}

// ---------------------------------------------------------------------------
// bits -> eps = sqrt(2)*erfinv(u), sqrt(2) folded into coefficients.
// Central poly truncated to 5 coefficients (dropped wc^5/wc^6 terms:
// <=1.8e-3 eps err at the |wc|=2.5 edge, ~3e-4 typical — inside the 1e-3
// output budget per the R8-measured error scaling). Tail branch unchanged.
// ---------------------------------------------------------------------------
__device__ __forceinline__ float bits_to_eps(uint32_t bits) {
    float v = (float)(bits >> 9);
    float u = __fmaf_rn(v, 0x1p-22f, -0.99999994f);

    float t = __fmul_rn(u, u);
    float y = __fadd_rn(1.0f, -t);
    float l = __log2f(y);
    float wc = __fmaf_rn(l, -0.69314718f, -2.5f);   // w - 2.5

    float p;
    p = 3.0911997e-04f;
    p = __fmaf_rn(p, wc, -1.7730364e-03f);
    p = __fmaf_rn(p, wc, -5.9081367e-03f);
    p = __fmaf_rn(p, wc, 3.4880266e-01f);
    p = __fmaf_rn(p, wc, 2.1233135e+00f);

    if (wc >= 2.5f) {   // rare tail: |u| > 0.99666
        float w  = __fmul_rn(l, -0.69314718f);
        float ws = __fsqrt_rn(w) - 3.0f;
        p = -2.8314684e-04f;
        p = __fmaf_rn(p, ws, 1.4276590e-04f);
        p = __fmaf_rn(p, ws, 1.9082523e-03f);
        p = __fmaf_rn(p, ws, -5.1950109e-03f);
        p = __fmaf_rn(p, ws, 8.1168911e-03f);
        p = __fmaf_rn(p, ws, -1.0779785e-02f);
        p = __fmaf_rn(p, ws, 1.3348580e-02f);
        p = __fmaf_rn(p, ws, 1.4165810e+00f);
        p = __fmaf_rn(p, ws, 4.0064341e+00f);
    }
    return __fmul_rn(p, u);
}

// ---------------------------------------------------------------------------
// grid = OUT_*4: block = (output column o, s-quarter q). 8 samples per block
// in registers; 256 threads stride IN. counter = s*2^22 + (o*IN + i).
// ---------------------------------------------------------------------------
__global__ void __launch_bounds__(TPB)
bayes_linear_kernel(const float* __restrict__ x,
                    const float* __restrict__ wmu,
                    const float* __restrict__ wsig,
                    const float* __restrict__ bmu,
                    const float* __restrict__ bsig,
                    float* __restrict__ out,
                    TFKeys wk, TFKeys bk, RotM rm,
                    uint32_t one, uint32_t c22 /* == 1<<22, opaque */)
{
    __shared__ float red[SGRP][(TPB / 32) + 1];   // [sample][warp] partials

    const int bid  = blockIdx.x;
    const int o    = bid & (OUT_ - 1);
    const int q    = bid >> 11;                   // s-quarter
    const int sbase = q * SGRP;
    const int tid  = threadIdx.x;
    const int lane = tid & 31;
    const int warp = tid >> 5;
    const uint32_t base_o = (uint32_t)o * (uint32_t)IN_;

    float acc[SGRP];
#pragma unroll
    for (int j = 0; j < SGRP; ++j) acc[j] = 0.0f;

#pragma unroll 1
    for (int ii = 0; ii < IN_ / TPB; ++ii) {
        const int i = ii * TPB + tid;
        const float mu = wmu[base_o + i];
        const float sg = wsig[base_o + i];
        const float* xp = x + (size_t)sbase * IN_ + i;

        // x1 init for j=0: sbase*2^22 + (base + i) + k1 ; per-j adds j*2^22
        const uint32_t cb = addi((uint32_t)sbase,
                                 base_o + (uint32_t)i + wk.k1, c22);

#pragma unroll
        for (int j = 0; j < SGRP; ++j) {
            const uint32_t bits = threefry_from_x1(wk, cb + ((uint32_t)j << 22), one, rm);
            const float eps = bits_to_eps(bits);
            acc[j] = __fmaf_rn(__fmaf_rn(sg, eps, mu), xp[j * IN_], acc[j]);
        }
    }

    // warp butterfly reduction; lane 0 stores the 8 partials
#pragma unroll
    for (int j = 0; j < SGRP; ++j) {
#pragma unroll
        for (int m = 16; m >= 1; m >>= 1)
            acc[j] += __shfl_xor_sync(0xffffffffu, acc[j], m);
    }
    if (lane == 0) {
#pragma unroll
        for (int j = 0; j < SGRP; ++j)
            red[j][warp] = acc[j];
    }

    __syncthreads();

    if (tid < SGRP) {
        float tot = 0.0f;
#pragma unroll
        for (int w = 0; w < TPB / 32; ++w) tot += red[tid][w];

        const int s = sbase + tid;
        // bias epsilon: counter = s*OUT + o over bkey (sqrt2 already folded)
        const uint32_t c1 = (uint32_t)(s * OUT_ + o);
        const float eb = bits_to_eps(threefry_from_x1(bk, c1 + bk.k1, one, rm));
        out[s * OUT_ + o] = tot + __fmaf_rn(bsig[o], eb, bmu[o]);
    }
}

// ---------------------------------------------------------------------------
extern "C" void kernel_launch(void* const* d_in, const int* in_sizes, int n_in,
                              void* d_out, int out_size)
{
    const float* x    = (const float*)d_in[0];
    const float* wmu  = (const float*)d_in[1];
    const float* wsig = (const float*)d_in[2];
    const float* bmu  = (const float*)d_in[3];
    const float* bsig = (const float*)d_in[4];
    float* out        = (float*)d_out;

    uint32_t wk0, wk1, bk0, bk1;
    h_threefry2x32(0u, 42u, 0u, 0u, wk0, wk1);
    h_threefry2x32(0u, 42u, 0u, 1u, bk0, bk1);

    TFKeys wk, bk;
    wk.k0 = wk0; wk.k1 = wk1; wk.k2 = wk0 ^ wk1 ^ 0x1BD11BDAu;
    wk.j1 = wk.k2 + 1u; wk.j2 = wk.k0 + 2u; wk.j3 = wk.k1 + 3u;
    wk.j4 = wk.k2 + 4u; wk.j5 = wk.k0 + 5u;

    bk.k0 = bk0; bk.k1 = bk1; bk.k2 = bk0 ^ bk1 ^ 0x1BD11BDAu;
    bk.j1 = bk.k2 + 1u; bk.j2 = bk.k0 + 2u; bk.j3 = bk.k1 + 3u;
    bk.j4 = bk.k2 + 4u; bk.j5 = bk.k0 + 5u;

    RotM rm;
    rm.m13 = 1u << 13; rm.m15 = 1u << 15; rm.m26 = 1u << 26; rm.m6  = 1u << 6;
    rm.m17 = 1u << 17; rm.m29 = 1u << 29; rm.m16 = 1u << 16; rm.m24 = 1u << 24;

    bayes_linear_kernel<<<OUT_ * QBLK, TPB>>>(x, wmu, wsig, bmu, bsig, out,
                                              wk, bk, rm, 1u, 1u << 22);
}

// round 10
// speedup vs baseline: 1.5186x; 1.5186x over previous
#include <cuda_runtime.h>
#include <cstdint>

#define S_    32
#define IN_   2048
#define OUT_  2048
#define TPB   256
#define SGRP  8                   // samples per block
#define QBLK  (S_ / SGRP)         // 4 s-quarters -> grid = OUT_ * QBLK
#define IN2   (IN_ / 2)           // float2 elements per row

// ---------------------------------------------------------------------------
// Host-side threefry2x32 (subkey derivation for jax.random.key(42) only)
// ---------------------------------------------------------------------------
static inline uint32_t h_rotl32(uint32_t x, int r) {
    return (x << r) | (x >> (32 - r));
}
static inline void h_round(uint32_t& x0, uint32_t& x1, int r) {
    x0 += x1; x1 = h_rotl32(x1, r); x1 ^= x0;
}
static void h_threefry2x32(uint32_t k0, uint32_t k1, uint32_t c0, uint32_t c1,
                           uint32_t& o0, uint32_t& o1)
{
    const uint32_t k2 = k0 ^ k1 ^ 0x1BD11BDAu;
    uint32_t x0 = c0 + k0, x1 = c1 + k1;
    h_round(x0,x1,13); h_round(x0,x1,15); h_round(x0,x1,26); h_round(x0,x1,6);
    x0 += k1; x1 += k2 + 1u;
    h_round(x0,x1,17); h_round(x0,x1,29); h_round(x0,x1,16); h_round(x0,x1,24);
    x0 += k2; x1 += k0 + 2u;
    h_round(x0,x1,13); h_round(x0,x1,15); h_round(x0,x1,26); h_round(x0,x1,6);
    x0 += k0; x1 += k1 + 3u;
    h_round(x0,x1,17); h_round(x0,x1,29); h_round(x0,x1,16); h_round(x0,x1,24);
    x0 += k1; x1 += k2 + 4u;
    h_round(x0,x1,13); h_round(x0,x1,15); h_round(x0,x1,26); h_round(x0,x1,6);
    x0 += k2; x1 += k0 + 5u;
    o0 = x0; o1 = x1;
}

// ---------------------------------------------------------------------------
// Device threefry (R4/R8 proven form): adds as IMAD (full-rate fma pipe,
// opaque `one`), SHF+LOP3 on alu. mul.wide rotate measured 2-slot -> rejected.
// ---------------------------------------------------------------------------
struct TFKeys {
    uint32_t k0, k1, k2;
    uint32_t j1, j2, j3, j4, j5;   // k2+1, k0+2, k1+3, k2+4, k0+5
};

__device__ __forceinline__ uint32_t addi(uint32_t a, uint32_t b, uint32_t one) {
    return a * one + b;            // IMAD -> fma pipe
}
__device__ __forceinline__ void tfr(uint32_t& x0, uint32_t& x1, int r, uint32_t one) {
    x0 = addi(x0, x1, one);
    x1 = __funnelshift_l(x1, x1, r);
    x1 ^= x0;
}
__device__ __forceinline__ uint32_t threefry_from_x1(const TFKeys k, uint32_t x1, uint32_t one) {
    uint32_t x0 = k.k0;            // c0 == 0

    tfr(x0,x1,13,one); tfr(x0,x1,15,one); tfr(x0,x1,26,one); tfr(x0,x1,6,one);
    x0 = addi(x0, k.k1, one); x1 = addi(x1, k.j1, one);
    tfr(x0,x1,17,one); tfr(x0,x1,29,one); tfr(x0,x1,16,one); tfr(x0,x1,24,one);
    x0 = addi(x0, k.k2, one); x1 = addi(x1, k.j2, one);
    tfr(x0,x1,13,one); tfr(x0,x1,15,one); tfr(x0,x1,26,one); tfr(x0,x1,6,one);
    x0 = addi(x0, k.k0, one); x1 = addi(x1, k.j3, one);
    tfr(x0,x1,17,one); tfr(x0,x1,29,one); tfr(x0,x1,16,one); tfr(x0,x1,24,one);
    x0 = addi(x0, k.k1, one); x1 = addi(x1, k.j4, one);
    tfr(x0,x1,13,one); tfr(x0,x1,15,one); tfr(x0,x1,26,one); tfr(x0,x1,6,one);
    x0 = addi(x0, k.k2, one); x1 = addi(x1, k.j5, one);

    return x0 ^ x1;
}

// ---------------------------------------------------------------------------
// bits -> eps = sqrt(2)*erfinv(u), sqrt(2) folded into the coefficients.
// Central poly: 5 coefficients (rel_err 1.33e-4 measured in R9 — 7.5x margin).
// Tail (P=0.37%/lane) divergent branch, poly trimmed to 5 coefficients
// (dropped terms matter only at w~16, P~1e-7; ~1e-5 rms).
// ---------------------------------------------------------------------------
__device__ __forceinline__ float bits_to_eps(uint32_t bits) {
    float v = (float)(bits >> 9);
    float u = __fmaf_rn(v, 0x1p-22f, -0.99999994f);

    float t = __fmul_rn(u, u);
    float y = __fadd_rn(1.0f, -t);
    float l = __log2f(y);
    float wc = __fmaf_rn(l, -0.69314718f, -2.5f);   // w - 2.5

    float p;
    p = 3.0911997e-04f;
    p = __fmaf_rn(p, wc, -1.7730364e-03f);
    p = __fmaf_rn(p, wc, -5.9081367e-03f);
    p = __fmaf_rn(p, wc, 3.4880266e-01f);
    p = __fmaf_rn(p, wc, 2.1233135e+00f);

    if (wc >= 2.5f) {   // rare tail: |u| > 0.99666
        float w  = __fmul_rn(l, -0.69314718f);
        float ws = __fsqrt_rn(w) - 3.0f;
        p = 8.1168911e-03f;
        p = __fmaf_rn(p, ws, -1.0779785e-02f);
        p = __fmaf_rn(p, ws, 1.3348580e-02f);
        p = __fmaf_rn(p, ws, 1.4165810e+00f);
        p = __fmaf_rn(p, ws, 4.0064341e+00f);
    }
    return __fmul_rn(p, u);
}

// ---------------------------------------------------------------------------
// grid = OUT_*4: block = (output column o, s-quarter q). 8 samples per block
// in registers. Each thread owns a float2 i-pair per iteration: x/mu/sigma
// via 8-byte loads (half the LDG issue), counters (i, i+1) consecutive.
// counter = s*2^22 + (o*IN + i).
// ---------------------------------------------------------------------------
__global__ void __launch_bounds__(TPB)
bayes_linear_kernel(const float* __restrict__ xf,
                    const float* __restrict__ wmuf,
                    const float* __restrict__ wsigf,
                    const float* __restrict__ bmu,
                    const float* __restrict__ bsig,
                    float* __restrict__ out,
                    TFKeys wk, TFKeys bk,
                    uint32_t one, uint32_t c22 /* == 1<<22, opaque */)
{
    __shared__ float red[SGRP][(TPB / 32) + 1];   // [sample][warp] partials

    const float2* __restrict__ x2   = (const float2*)xf;
    const float2* __restrict__ wmu2 = (const float2*)wmuf;
    const float2* __restrict__ wsg2 = (const float2*)wsigf;

    const int bid   = blockIdx.x;
    const int o     = bid & (OUT_ - 1);
    const int q     = bid >> 11;                  // s-quarter
    const int sbase = q * SGRP;
    const int tid   = threadIdx.x;
    const int lane  = tid & 31;
    const int warp  = tid >> 5;
    const uint32_t base_o  = (uint32_t)o * (uint32_t)IN_;
    const int      base_o2 = o * IN2;

    float acc[SGRP];
#pragma unroll
    for (int j = 0; j < SGRP; ++j) acc[j] = 0.0f;

#pragma unroll 1
    for (int it = 0; it < IN2 / TPB; ++it) {
        const int p = it * TPB + tid;             // float2 index, i = 2p
        const float2 mu2 = wmu2[base_o2 + p];
        const float2 sg2 = wsg2[base_o2 + p];
        const float2* xp2 = x2 + (size_t)sbase * IN2 + p;

        // x1 init for j=0,d=0: sbase*2^22 + (base_o + 2p) + k1
        const uint32_t cb = addi((uint32_t)sbase,
                                 base_o + (uint32_t)(2 * p) + wk.k1, c22);

#pragma unroll
        for (int j = 0; j < SGRP; ++j) {
            const uint32_t cj = cb + ((uint32_t)j << 22);
            const float2 xv = xp2[j * IN2];

            const uint32_t bits0 = threefry_from_x1(wk, cj,      one);
            const uint32_t bits1 = threefry_from_x1(wk, cj + 1u, one);
            const float eps0 = bits_to_eps(bits0);
            const float eps1 = bits_to_eps(bits1);

            acc[j] = __fmaf_rn(__fmaf_rn(sg2.x, eps0, mu2.x), xv.x, acc[j]);
            acc[j] = __fmaf_rn(__fmaf_rn(sg2.y, eps1, mu2.y), xv.y, acc[j]);
        }
    }

    // warp butterfly reduction; lane 0 stores the 8 partials
#pragma unroll
    for (int j = 0; j < SGRP; ++j) {
#pragma unroll
        for (int m = 16; m >= 1; m >>= 1)
            acc[j] += __shfl_xor_sync(0xffffffffu, acc[j], m);
    }
    if (lane == 0) {
#pragma unroll
        for (int j = 0; j < SGRP; ++j)
            red[j][warp] = acc[j];
    }

    __syncthreads();

    if (tid < SGRP) {
        float tot = 0.0f;
#pragma unroll
        for (int w = 0; w < TPB / 32; ++w) tot += red[tid][w];

        const int s = sbase + tid;
        // bias epsilon: counter = s*OUT + o over bkey (sqrt2 already folded)
        const uint32_t c1 = (uint32_t)(s * OUT_ + o);
        const float eb = bits_to_eps(threefry_from_x1(bk, c1 + bk.k1, one));
        out[s * OUT_ + o] = tot + __fmaf_rn(bsig[o], eb, bmu[o]);
    }
}

// ---------------------------------------------------------------------------
extern "C" void kernel_launch(void* const* d_in, const int* in_sizes, int n_in,
                              void* d_out, int out_size)
{
    const float* x    = (const float*)d_in[0];
    const float* wmu  = (const float*)d_in[1];
    const float* wsig = (const float*)d_in[2];
    const float* bmu  = (const float*)d_in[3];
    const float* bsig = (const float*)d_in[4];
    float* out        = (float*)d_out;

    uint32_t wk0, wk1, bk0, bk1;
    h_threefry2x32(0u, 42u, 0u, 0u, wk0, wk1);
    h_threefry2x32(0u, 42u, 0u, 1u, bk0, bk1);

    TFKeys wk, bk;
    wk.k0 = wk0; wk.k1 = wk1; wk.k2 = wk0 ^ wk1 ^ 0x1BD11BDAu;
    wk.j1 = wk.k2 + 1u; wk.j2 = wk.k0 + 2u; wk.j3 = wk.k1 + 3u;
    wk.j4 = wk.k2 + 4u; wk.j5 = wk.k0 + 5u;

    bk.k0 = bk0; bk.k1 = bk1; bk.k2 = bk0 ^ bk1 ^ 0x1BD11BDAu;
    bk.j1 = bk.k2 + 1u; bk.j2 = bk.k0 + 2u; bk.j3 = bk.k1 + 3u;
    bk.j4 = bk.k2 + 4u; bk.j5 = bk.k0 + 5u;

    bayes_linear_kernel<<<OUT_ * QBLK, TPB>>>(x, wmu, wsig, bmu, bsig, out,
                                              wk, bk, 1u, 1u << 22);
}